// round 15
// baseline (speedup 1.0000x reference)
#include <cuda_runtime.h>
#include <cuda_bf16.h>
#include <cstdint>

// Problem constants
#define BB 16
#define CC 128
#define PP 512
#define TT 32
#define HH 2
#define DD 64
#define EE (DD * TT)   // 2048
#define O3 (3 * CC)    // 384
#define NN ((size_t)BB * PP * TT)   // 262144 columns of the QKV GEMM

// ======================== mma.sync helpers ========================
static __device__ __forceinline__ uint32_t smem_u32(const void* p) {
    uint32_t a;
    asm("{ .reg .u64 t; cvta.to.shared.u64 t, %1; cvt.u32.u64 %0, t; }" : "=r"(a) : "l"(p));
    return a;
}
#define LDSM4(r0, r1, r2, r3, a) \
    asm volatile("ldmatrix.sync.aligned.m8n8.x4.shared.b16 {%0,%1,%2,%3}, [%4];" \
        : "=r"(r0), "=r"(r1), "=r"(r2), "=r"(r3) : "r"(a))
#define LDSM4T(r0, r1, r2, r3, a) \
    asm volatile("ldmatrix.sync.aligned.m8n8.x4.trans.shared.b16 {%0,%1,%2,%3}, [%4];" \
        : "=r"(r0), "=r"(r1), "=r"(r2), "=r"(r3) : "r"(a))
#define MMA16816(d, a, b) \
    asm volatile("mma.sync.aligned.m16n8k16.row.col.f32.bf16.bf16.f32 " \
        "{%0,%1,%2,%3}, {%4,%5,%6,%7}, {%8,%9}, {%0,%1,%2,%3};" \
        : "+f"((d)[0]), "+f"((d)[1]), "+f"((d)[2]), "+f"((d)[3]) \
        : "r"((a)[0]), "r"((a)[1]), "r"((a)[2]), "r"((a)[3]), "r"((b)[0]), "r"((b)[1]))
#define CP_ASYNC16(s, g) \
    asm volatile("cp.async.cg.shared.global [%0], [%1], 16;" :: "r"(s), "l"(g) : "memory")
#define CP_COMMIT() asm volatile("cp.async.commit_group;" ::: "memory")
#define STS64(addr, v) asm volatile("st.shared.b64 [%0], %1;" :: "r"(addr), "l"(v) : "memory")

// ======================== scratch (device globals) ========================
__device__ __nv_bfloat16 g_w_hi[O3 * CC];
__device__ __nv_bfloat16 g_w_lo[O3 * CC];
__device__ __nv_bfloat16 g_q_hi[(size_t)BB * HH * PP * EE];
__device__ __nv_bfloat16 g_q_lo[(size_t)BB * HH * PP * EE];
__device__ __nv_bfloat16 g_k_hi[(size_t)BB * HH * PP * EE];
__device__ __nv_bfloat16 g_k_lo[(size_t)BB * HH * PP * EE];
__device__ __nv_bfloat16 g_v_hi[(size_t)BB * HH * PP * EE];   // [bh][q][e] natural
__device__ __nv_bfloat16 g_v_lo[(size_t)BB * HH * PP * EE];
__device__ float         g_dots[(size_t)BB * HH * PP * PP];
__device__ __nv_bfloat16 g_attn_hi[(size_t)BB * HH * PP * PP];
__device__ __nv_bfloat16 g_attn_lo[(size_t)BB * HH * PP * PP];

static __device__ __forceinline__ void split_bf16(float v, __nv_bfloat16& hi, __nv_bfloat16& lo) {
    hi = __float2bfloat16(v);
    lo = __float2bfloat16(v - __bfloat162float(hi));
}

// ---------------------------------------------------------------------------
// K0: split W -> bf16 hi/lo
// ---------------------------------------------------------------------------
__global__ void wsplit_kernel(const float* __restrict__ W) {
    int i = blockIdx.x * blockDim.x + threadIdx.x;
    if (i < O3 * CC) split_bf16(W[i], g_w_hi[i], g_w_lo[i]);
}

// ---------------------------------------------------------------------------
// MEDIUM GEMM (dots & out): block 128x128, 128 threads = 4 warps (2m x 2n),
// warp tile 64x64, KT=32, 3-stage ring (96 KB/CTA), 2 CTAs/SM.
// Term rotation: t1(ah,bh) -> t3(al,bh) -> t2(ah,bl), single-buffered frags.
// (Exact R9/R13 structure — proven 240.7us / 70.5% tensor on dots.)
// transB=0: B [N][K] k-major.  transB=1: B [K][N] n-major (ldsm.trans).
// mode 0: fp32 out (dots). mode 1: scatter to (B,C,P,T) output.
// ---------------------------------------------------------------------------
#define MSTAGE 32768
#define MED_SMEM_REQ (3 * MSTAGE + 1024)

__global__ void __launch_bounds__(128, 2) mma_med_kernel(
    const __nv_bfloat16* __restrict__ Ah, const __nv_bfloat16* __restrict__ Al,
    const __nv_bfloat16* __restrict__ Bh, const __nv_bfloat16* __restrict__ Bl,
    int Kdim, int bLd, int transB, size_t aStride, size_t bStride,
    int mode, float* __restrict__ dst)
{
    extern __shared__ char smem[];
    uint32_t base = (smem_u32(smem) + 1023) & ~1023u;

    int tid = threadIdx.x;
    int wid = tid >> 5, lane = tid & 31;
    int bh = blockIdx.z;
    int m0 = blockIdx.y * 128;
    int n0 = blockIdx.x * 128;

    const __nv_bfloat16* A0h = Ah + (size_t)bh * aStride;
    const __nv_bfloat16* A0l = Al + (size_t)bh * aStride;
    const __nv_bfloat16* B0h = Bh + (size_t)bh * bStride;
    const __nv_bfloat16* B0l = Bl + (size_t)bh * bStride;

    // stage layout: A-hi 8KB | A-lo 8KB | B-hi 8KB | B-lo 8KB
    auto load_tiles = [&](int it) {
        int kk = it * 32;
        uint32_t db = base + (uint32_t)(it % 3) * MSTAGE;
#pragma unroll
        for (int i = 0; i < 8; i++) {            // A: 128 rows x 64B x2 tiles
            const int tile = i >> 2;
            int c = tid + (i & 3) * 128;
            int r = (c >> 2) & 127;
            int j = c & 3;
            const __nv_bfloat16* g = (tile ? A0l : A0h)
                + (size_t)(m0 + r) * Kdim + (kk + j * 8);
            uint32_t s = db + tile * 8192 + r * 64 + (((j ^ ((r >> 1) & 3))) << 4);
            CP_ASYNC16(s, g);
        }
        if (!transB) {
#pragma unroll
            for (int i = 0; i < 8; i++) {        // B: 128 rows x 64B x2
                const int tile = i >> 2;
                int c = tid + (i & 3) * 128;
                int r = (c >> 2) & 127;
                int j = c & 3;
                const __nv_bfloat16* g = (tile ? B0l : B0h)
                    + (size_t)(n0 + r) * bLd + (kk + j * 8);
                uint32_t s = db + 16384 + tile * 8192 + r * 64 + (((j ^ ((r >> 1) & 3))) << 4);
                CP_ASYNC16(s, g);
            }
        } else {
#pragma unroll
            for (int i = 0; i < 8; i++) {        // B: 32 k-rows x 256B x2
                const int tile = i >> 2;
                int c = tid + (i & 3) * 128;
                int r = (c >> 4) & 31;
                int j = c & 15;
                const __nv_bfloat16* g = (tile ? B0l : B0h)
                    + (size_t)(kk + r) * bLd + (n0 + j * 8);
                uint32_t s = db + 16384 + tile * 8192 + r * 256 + (((j ^ (r & 7))) << 4);
                CP_ASYNC16(s, g);
            }
        }
        CP_COMMIT();
    };

    // warp coords: 2m x 2n, warp tile 64x64
    int warp_m = wid & 1, warp_n = wid >> 1;
    int row_in = lane & 7, mat = lane >> 3;
    int a_row = warp_m * 64 + (mat & 1) * 8 + row_in;     // + mt*16
    uint32_t a_salt = (uint32_t)((a_row >> 1) & 3);
    int a_jk = (mat >> 1);
    int b_row = warp_n * 64 + (mat >> 1) * 8 + row_in;    // + ntp*16 (NT)
    uint32_t b_salt = (uint32_t)((b_row >> 1) & 3);
    int b_jk = (mat & 1);
    int t_krow_in = (mat & 1) * 8 + row_in;               // trans-B
    int t_jbase = warp_n * 8 + (mat >> 1);

    float acc[4][8][4];
#pragma unroll
    for (int i = 0; i < 4; i++)
#pragma unroll
        for (int j = 0; j < 8; j++)
#pragma unroll
            for (int k = 0; k < 4; k++) acc[i][j][k] = 0.f;

    // fragment load helpers (single-buffered)
    uint32_t ah[4][4], alf[4][4], bhf[8][2], blf[8][2];
    auto load_a = [&](uint32_t Ab, int kq, uint32_t (*fr)[4]) {
        int aj = kq * 2 + a_jk;
#pragma unroll
        for (int mt = 0; mt < 4; mt++) {
            uint32_t ad = Ab + (uint32_t)(a_row + mt * 16) * 64
                        + (((uint32_t)aj ^ a_salt) << 4);
            LDSM4(fr[mt][0], fr[mt][1], fr[mt][2], fr[mt][3], ad);
        }
    };
    auto load_b = [&](uint32_t Bb, int kq, uint32_t (*fr)[2]) {
        if (!transB) {
            int bj = kq * 2 + b_jk;
#pragma unroll
            for (int ntp = 0; ntp < 4; ntp++) {
                uint32_t ad = Bb + (uint32_t)(b_row + ntp * 16) * 64
                            + (((uint32_t)bj ^ b_salt) << 4);
                uint32_t r0, r1, r2, r3;
                LDSM4(r0, r1, r2, r3, ad);
                fr[2 * ntp][0] = r0; fr[2 * ntp][1] = r1;
                fr[2 * ntp + 1][0] = r2; fr[2 * ntp + 1][1] = r3;
            }
        } else {
            uint32_t krow = (uint32_t)(kq * 16 + t_krow_in);
            uint32_t sw = (uint32_t)(t_krow_in & 7);
#pragma unroll
            for (int ntp = 0; ntp < 4; ntp++) {
                uint32_t j = (uint32_t)(t_jbase + ntp * 2);
                uint32_t ad = Bb + krow * 256 + ((j ^ sw) << 4);
                uint32_t r0, r1, r2, r3;
                LDSM4T(r0, r1, r2, r3, ad);
                fr[2 * ntp][0] = r0; fr[2 * ntp][1] = r1;
                fr[2 * ntp + 1][0] = r2; fr[2 * ntp + 1][1] = r3;
            }
        }
    };
    auto mma_term = [&](uint32_t (*af)[4], uint32_t (*bf)[2]) {
#pragma unroll
        for (int mt = 0; mt < 4; mt++)
#pragma unroll
            for (int nt = 0; nt < 8; nt++)
                MMA16816(acc[mt][nt], af[mt], bf[nt]);
    };

    int iters = Kdim / 32;
    load_tiles(0);
    if (iters > 1) load_tiles(1);

    for (int it = 0; it < iters; it++) {
        if (it + 1 < iters) {
            asm volatile("cp.async.wait_group 1;" ::: "memory");
        } else {
            asm volatile("cp.async.wait_group 0;" ::: "memory");
        }
        __syncthreads();
        if (it + 2 < iters) load_tiles(it + 2);

        uint32_t db = base + (uint32_t)(it % 3) * MSTAGE;
        uint32_t Ah_b = db, Al_b = db + 8192, Bh_b = db + 16384, Bl_b = db + 24576;

        // kq0
        load_a(Ah_b, 0, ah);
        load_b(Bh_b, 0, bhf);
        load_a(Al_b, 0, alf);           // al0 ahead of term1
        mma_term(ah, bhf);              // term1: ah0*bh0
        load_b(Bl_b, 0, blf);           // bl0 ahead of term3
        mma_term(alf, bhf);             // term3: al0*bh0   (bh0 dead after)
        load_b(Bh_b, 1, bhf);           // bh1 — overwrites dead bh0
        mma_term(ah, blf);              // term2: ah0*bl0   (ah0 dead after)
        // kq1
        load_a(Ah_b, 1, ah);            // ah1 — overwrites dead ah0
        load_a(Al_b, 1, alf);           // al1 ahead of term1
        mma_term(ah, bhf);              // term1: ah1*bh1
        load_b(Bl_b, 1, blf);           // bl1 ahead of term3
        mma_term(alf, bhf);             // term3: al1*bh1
        mma_term(ah, blf);              // term2: ah1*bl1
    }

    // ---- epilogue ----
    int gm = m0 + warp_m * 64 + (lane >> 2);
    if (mode == 0) {
#pragma unroll
        for (int mt = 0; mt < 4; mt++)
#pragma unroll
            for (int nt = 0; nt < 8; nt++) {
                int col = n0 + warp_n * 64 + nt * 8 + (lane & 3) * 2;
                int row = gm + mt * 16;
                float* d0 = dst + ((size_t)bh * PP + row) * PP + col;
                *(float2*)d0 = make_float2(acc[mt][nt][0], acc[mt][nt][1]);
                *(float2*)(d0 + 8 * PP) = make_float2(acc[mt][nt][2], acc[mt][nt][3]);
            }
    } else {
        int b = bh >> 1, h = bh & 1;
#pragma unroll
        for (int mt = 0; mt < 4; mt++)
#pragma unroll
            for (int nt = 0; nt < 8; nt++) {
                int e = n0 + warp_n * 64 + nt * 8 + (lane & 3) * 2;
                int d = e >> 5, t = e & 31;
                int p = gm + mt * 16;
                float* d0 = dst + (((size_t)b * CC + h * DD + d) * PP + p) * TT + t;
                *(float2*)d0 = make_float2(acc[mt][nt][0], acc[mt][nt][1]);
                *(float2*)(d0 + 8 * TT) = make_float2(acc[mt][nt][2], acc[mt][nt][3]);
            }
    }
}

// ---------------------------------------------------------------------------
// QKV GEMM v3b: reads x DIRECTLY (no xsplit kernel). B (x-tile 128n x 128c)
// is converted to bf16 hi/lo splits in a prologue and stored RESIDENT in smem
// in the trans-B layout (4 k-stages of 32 c-rows x 256B, swizzle j^(r&7)).
// A = W through a 3-STAGE cp.async ring (fix of the R14 2-stage WAR race:
// prefetch distance 2 must land on a disjoint stage).
// Block 128x128, 128 threads (2m x 2n warps, 64x64), 2 CTAs/SM.
// smem: B 64KB resident | A ring 3x16KB = 112KB + pad.
// grid: (n-tile 2048, kind 3). Epilogue: +bias, q-scale, split-store q/k/v.
// ---------------------------------------------------------------------------
#define QA_STAGE 16384
#define QKV_SMEM_REQ (65536 + 3 * QA_STAGE + 1024)

__global__ void __launch_bounds__(128, 2) qkv_kernel(
    const __nv_bfloat16* __restrict__ Wh, const __nv_bfloat16* __restrict__ Wl,
    const float* __restrict__ x, const float* __restrict__ bias)
{
    extern __shared__ char smem[];
    uint32_t bbase = (smem_u32(smem) + 1023) & ~1023u;   // B resident: 64KB
    uint32_t abase = bbase + 65536;                      // A ring: 3x16KB

    int tid = threadIdx.x;
    int wid = tid >> 5, lane = tid & 31;
    int n0 = blockIdx.x * 128;
    int kind = blockIdx.y;
    int m0 = kind * 128;

    // ---- A (W) loader: 128 rows x 64B hi+lo into stage it%3 ----
    auto load_tiles = [&](int it) {
        int kk = it * 32;
        uint32_t db = abase + (uint32_t)(it % 3) * QA_STAGE;
#pragma unroll
        for (int i = 0; i < 8; i++) {
            const int tile = i >> 2;
            int c = tid + (i & 3) * 128;
            int r = (c >> 2) & 127;
            int j = c & 3;
            const __nv_bfloat16* g = (tile ? Wl : Wh)
                + (size_t)(m0 + r) * CC + (kk + j * 8);
            uint32_t s = db + tile * 8192 + r * 64 + (((j ^ ((r >> 1) & 3))) << 4);
            CP_ASYNC16(s, g);
        }
        CP_COMMIT();
    };

    load_tiles(0);
    load_tiles(1);

    // ---- B prologue: read x directly, split, store resident trans-B tiles.
    // x[b][c][p][t]; n0 block lies in one batch. For fixed c the 128 n's are
    // contiguous. warp w handles c = 4i + w; lane covers n = 4*lane..+3.
    {
        int b0 = (int)((unsigned)n0 >> 14);
        int loc = n0 & 16383;
        const float* xb = x + (size_t)b0 * CC * (PP * TT) + loc;
#pragma unroll 4
        for (int i = 0; i < 32; i++) {
            int c = i * 4 + wid;
            float4 v = *(const float4*)(xb + (size_t)c * (PP * TT) + 4 * lane);
            __nv_bfloat16 h[4], l[4];
            split_bf16(v.x, h[0], l[0]);
            split_bf16(v.y, h[1], l[1]);
            split_bf16(v.z, h[2], l[2]);
            split_bf16(v.w, h[3], l[3]);
            int s = c >> 5, r = c & 31;
            uint32_t j = (uint32_t)(lane >> 1);
            uint32_t off = (uint32_t)r * 256 + ((j ^ (uint32_t)(r & 7)) << 4)
                         + (uint32_t)(lane & 1) * 8;
            uint32_t rowb = bbase + (uint32_t)s * 16384;
            STS64(rowb + off, *(const unsigned long long*)h);
            STS64(rowb + 8192 + off, *(const unsigned long long*)l);
        }
    }

    // ---- mainloop (med body, transB, Kdim=128 -> 4 iters) ----
    int warp_m = wid & 1, warp_n = wid >> 1;
    int row_in = lane & 7, mat = lane >> 3;
    int a_row = warp_m * 64 + (mat & 1) * 8 + row_in;
    uint32_t a_salt = (uint32_t)((a_row >> 1) & 3);
    int a_jk = (mat >> 1);
    int t_krow_in = (mat & 1) * 8 + row_in;
    int t_jbase = warp_n * 8 + (mat >> 1);

    float acc[4][8][4];
#pragma unroll
    for (int i = 0; i < 4; i++)
#pragma unroll
        for (int j = 0; j < 8; j++)
#pragma unroll
            for (int k = 0; k < 4; k++) acc[i][j][k] = 0.f;

    uint32_t ah[4][4], alf[4][4], bhf[8][2], blf[8][2];
    auto load_a = [&](uint32_t Ab, int kq, uint32_t (*fr)[4]) {
        int aj = kq * 2 + a_jk;
#pragma unroll
        for (int mt = 0; mt < 4; mt++) {
            uint32_t ad = Ab + (uint32_t)(a_row + mt * 16) * 64
                        + (((uint32_t)aj ^ a_salt) << 4);
            LDSM4(fr[mt][0], fr[mt][1], fr[mt][2], fr[mt][3], ad);
        }
    };
    auto load_b = [&](uint32_t Bb, int kq, uint32_t (*fr)[2]) {
        uint32_t krow = (uint32_t)(kq * 16 + t_krow_in);
        uint32_t sw = (uint32_t)(t_krow_in & 7);
#pragma unroll
        for (int ntp = 0; ntp < 4; ntp++) {
            uint32_t j = (uint32_t)(t_jbase + ntp * 2);
            uint32_t ad = Bb + krow * 256 + ((j ^ sw) << 4);
            uint32_t r0, r1, r2, r3;
            LDSM4T(r0, r1, r2, r3, ad);
            fr[2 * ntp][0] = r0; fr[2 * ntp][1] = r1;
            fr[2 * ntp + 1][0] = r2; fr[2 * ntp + 1][1] = r3;
        }
    };
    auto mma_term = [&](uint32_t (*af)[4], uint32_t (*bf)[2]) {
#pragma unroll
        for (int mt = 0; mt < 4; mt++)
#pragma unroll
            for (int nt = 0; nt < 8; nt++)
                MMA16816(acc[mt][nt], af[mt], bf[nt]);
    };

#pragma unroll
    for (int it = 0; it < 4; it++) {
        if (it + 1 < 4) {
            asm volatile("cp.async.wait_group 1;" ::: "memory");
        } else {
            asm volatile("cp.async.wait_group 0;" ::: "memory");
        }
        __syncthreads();                 // covers B prologue at it=0, A ring reuse
        if (it + 2 < 4) load_tiles(it + 2);   // stage (it+2)%3 — disjoint

        uint32_t db = abase + (uint32_t)(it % 3) * QA_STAGE;
        uint32_t Ah_b = db, Al_b = db + 8192;
        uint32_t Bh_b = bbase + (uint32_t)it * 16384, Bl_b = Bh_b + 8192;

        // kq0
        load_a(Ah_b, 0, ah);
        load_b(Bh_b, 0, bhf);
        load_a(Al_b, 0, alf);
        mma_term(ah, bhf);
        load_b(Bl_b, 0, blf);
        mma_term(alf, bhf);
        load_b(Bh_b, 1, bhf);
        mma_term(ah, blf);
        // kq1
        load_a(Ah_b, 1, ah);
        load_a(Al_b, 1, alf);
        mma_term(ah, bhf);
        load_b(Bl_b, 1, blf);
        mma_term(alf, bhf);
        mma_term(ah, blf);
    }

    // ---- epilogue: +bias, q-scale, bf16 split-store into q/k/v layouts ----
    __nv_bfloat16* dh = (kind == 0) ? g_q_hi : (kind == 1) ? g_k_hi : g_v_hi;
    __nv_bfloat16* dl = (kind == 0) ? g_q_lo : (kind == 1) ? g_k_lo : g_v_lo;
    float mul = (kind == 0) ? 0.125f : 1.0f;
#pragma unroll
    for (int mt = 0; mt < 4; mt++)
#pragma unroll
        for (int nt = 0; nt < 8; nt++) {
            int n = n0 + warp_n * 64 + nt * 8 + (lane & 3) * 2;
            int b = n >> 14;
            int p = (n >> 5) & (PP - 1);
            int t = n & (TT - 1);
#pragma unroll
            for (int half = 0; half < 2; half++) {
                int o = warp_m * 64 + mt * 16 + (lane >> 2) + half * 8;  // 0..127
                float bv = __ldg(&bias[kind * CC + o]);
                int h = o >> 6, d = o & (DD - 1);
                float v0 = (acc[mt][nt][2 * half + 0] + bv) * mul;
                float v1 = (acc[mt][nt][2 * half + 1] + bv) * mul;
                __nv_bfloat16 h2[2], l2[2];
                split_bf16(v0, h2[0], l2[0]);
                split_bf16(v1, h2[1], l2[1]);
                size_t off = (((size_t)b * HH + h) * PP + p) * EE + d * TT + t;
                *(uint32_t*)(dh + off) = *(const uint32_t*)h2;
                *(uint32_t*)(dl + off) = *(const uint32_t*)l2;
            }
        }
}

// ---------------------------------------------------------------------------
// K3: row softmax over g_dots; emits attn as bf16 hi/lo splits.
// ---------------------------------------------------------------------------
__global__ void __launch_bounds__(128) softmax_kernel() {
    size_t row = blockIdx.x;
    const float* r = g_dots + row * PP;
    int tid = threadIdx.x;
    float4 v = ((const float4*)r)[tid];

    float m = fmaxf(fmaxf(v.x, v.y), fmaxf(v.z, v.w));
#pragma unroll
    for (int o = 16; o; o >>= 1) m = fmaxf(m, __shfl_xor_sync(0xffffffffu, m, o));
    __shared__ float red[4];
    int wid = tid >> 5;
    if ((tid & 31) == 0) red[wid] = m;
    __syncthreads();
    m = fmaxf(fmaxf(red[0], red[1]), fmaxf(red[2], red[3]));

    v.x = expf(v.x - m); v.y = expf(v.y - m);
    v.z = expf(v.z - m); v.w = expf(v.w - m);
    float s = v.x + v.y + v.z + v.w;
#pragma unroll
    for (int o = 16; o; o >>= 1) s += __shfl_xor_sync(0xffffffffu, s, o);
    __syncthreads();
    if ((tid & 31) == 0) red[wid] = s;
    __syncthreads();
    float inv = 1.0f / (red[0] + red[1] + red[2] + red[3]);
    v.x *= inv; v.y *= inv; v.z *= inv; v.w *= inv;

    __nv_bfloat16 hi[4], lo[4];
    split_bf16(v.x, hi[0], lo[0]); split_bf16(v.y, hi[1], lo[1]);
    split_bf16(v.z, hi[2], lo[2]); split_bf16(v.w, hi[3], lo[3]);
    *(uint2*)(g_attn_hi + row * PP + tid * 4) = *(const uint2*)hi;
    *(uint2*)(g_attn_lo + row * PP + tid * 4) = *(const uint2*)lo;
}

// ---------------------------------------------------------------------------
extern "C" void kernel_launch(void* const* d_in, const int* in_sizes, int n_in,
                              void* d_out, int out_size) {
    const float* x = (const float*)d_in[0];
    const float* W = (const float*)d_in[1];
    const float* b = (const float*)d_in[2];
    float* out = (float*)d_out;

    cudaFuncSetAttribute(qkv_kernel, cudaFuncAttributeMaxDynamicSharedMemorySize, QKV_SMEM_REQ);
    cudaFuncSetAttribute(mma_med_kernel, cudaFuncAttributeMaxDynamicSharedMemorySize, MED_SMEM_REQ);

    wsplit_kernel<<<(O3 * CC + 255) / 256, 256>>>(W);

    // QKV: reads x directly (fused transpose+split prologue), mode-2 epilogue
    {
        __nv_bfloat16 *wh, *wl;
        cudaGetSymbolAddress((void**)&wh, g_w_hi);
        cudaGetSymbolAddress((void**)&wl, g_w_lo);
        dim3 g((unsigned)(NN / 128), O3 / 128, 1);
        qkv_kernel<<<g, 128, QKV_SMEM_REQ>>>(wh, wl, x, b);
    }

    // dots = Qs @ K^T : M=512, N=512, K=2048, NT, medium kernel mode 0
    {
        float* dots = nullptr;
        cudaGetSymbolAddress((void**)&dots, g_dots);
        __nv_bfloat16 *qh, *ql, *kh, *kl;
        cudaGetSymbolAddress((void**)&qh, g_q_hi);
        cudaGetSymbolAddress((void**)&ql, g_q_lo);
        cudaGetSymbolAddress((void**)&kh, g_k_hi);
        cudaGetSymbolAddress((void**)&kl, g_k_lo);
        dim3 g(PP / 128, PP / 128, BB * HH);
        mma_med_kernel<<<g, 128, MED_SMEM_REQ>>>(qh, ql, kh, kl, EE, EE, 0,
                                                 (size_t)PP * EE, (size_t)PP * EE, 0, dots);
    }

    softmax_kernel<<<BB * HH * PP, 128>>>();

    // out = attn @ V : M=512, N=2048(E), K=512, trans-B, medium kernel mode 1
    {
        __nv_bfloat16 *ah, *al, *vh, *vl;
        cudaGetSymbolAddress((void**)&ah, g_attn_hi);
        cudaGetSymbolAddress((void**)&al, g_attn_lo);
        cudaGetSymbolAddress((void**)&vh, g_v_hi);
        cudaGetSymbolAddress((void**)&vl, g_v_lo);
        dim3 g(EE / 128, PP / 128, BB * HH);
        mma_med_kernel<<<g, 128, MED_SMEM_REQ>>>(ah, al, vh, vl, PP, EE, 1,
                                                 (size_t)PP * PP, (size_t)PP * EE, 1, out);
    }
}

// round 16
// speedup vs baseline: 1.1372x; 1.1372x over previous
#include <cuda_runtime.h>
#include <cuda_bf16.h>
#include <cstdint>

// Problem constants
#define BB 16
#define CC 128
#define PP 512
#define TT 32
#define HH 2
#define DD 64
#define EE (DD * TT)   // 2048
#define O3 (3 * CC)    // 384
#define NN ((size_t)BB * PP * TT)   // 262144 columns of the QKV GEMM

// ======================== mma.sync helpers ========================
static __device__ __forceinline__ uint32_t smem_u32(const void* p) {
    uint32_t a;
    asm("{ .reg .u64 t; cvta.to.shared.u64 t, %1; cvt.u32.u64 %0, t; }" : "=r"(a) : "l"(p));
    return a;
}
#define LDSM4(r0, r1, r2, r3, a) \
    asm volatile("ldmatrix.sync.aligned.m8n8.x4.shared.b16 {%0,%1,%2,%3}, [%4];" \
        : "=r"(r0), "=r"(r1), "=r"(r2), "=r"(r3) : "r"(a))
#define LDSM4T(r0, r1, r2, r3, a) \
    asm volatile("ldmatrix.sync.aligned.m8n8.x4.trans.shared.b16 {%0,%1,%2,%3}, [%4];" \
        : "=r"(r0), "=r"(r1), "=r"(r2), "=r"(r3) : "r"(a))
#define MMA16816(d, a, b) \
    asm volatile("mma.sync.aligned.m16n8k16.row.col.f32.bf16.bf16.f32 " \
        "{%0,%1,%2,%3}, {%4,%5,%6,%7}, {%8,%9}, {%0,%1,%2,%3};" \
        : "+f"((d)[0]), "+f"((d)[1]), "+f"((d)[2]), "+f"((d)[3]) \
        : "r"((a)[0]), "r"((a)[1]), "r"((a)[2]), "r"((a)[3]), "r"((b)[0]), "r"((b)[1]))
#define CP_ASYNC16(s, g) \
    asm volatile("cp.async.cg.shared.global [%0], [%1], 16;" :: "r"(s), "l"(g) : "memory")
#define CP_COMMIT() asm volatile("cp.async.commit_group;" ::: "memory")

// ======================== scratch (device globals) ========================
__device__ __nv_bfloat16 g_w_hi[O3 * CC];
__device__ __nv_bfloat16 g_w_lo[O3 * CC];
__device__ __nv_bfloat16 g_xt_hi[NN * CC];    // [n=(b,p,t)][c]
__device__ __nv_bfloat16 g_xt_lo[NN * CC];
__device__ __nv_bfloat16 g_q_hi[(size_t)BB * HH * PP * EE];
__device__ __nv_bfloat16 g_q_lo[(size_t)BB * HH * PP * EE];
__device__ __nv_bfloat16 g_k_hi[(size_t)BB * HH * PP * EE];
__device__ __nv_bfloat16 g_k_lo[(size_t)BB * HH * PP * EE];
__device__ __nv_bfloat16 g_v_hi[(size_t)BB * HH * PP * EE];   // [bh][q][e] natural
__device__ __nv_bfloat16 g_v_lo[(size_t)BB * HH * PP * EE];
__device__ float         g_dots[(size_t)BB * HH * PP * PP];
__device__ __nv_bfloat16 g_attn_hi[(size_t)BB * HH * PP * PP];
__device__ __nv_bfloat16 g_attn_lo[(size_t)BB * HH * PP * PP];

static __device__ __forceinline__ void split_bf16(float v, __nv_bfloat16& hi, __nv_bfloat16& lo) {
    hi = __float2bfloat16(v);
    lo = __float2bfloat16(v - __bfloat162float(hi));
}

// ---------------------------------------------------------------------------
// K0: split W -> bf16 hi/lo
// ---------------------------------------------------------------------------
__global__ void wsplit_kernel(const float* __restrict__ W) {
    int i = blockIdx.x * blockDim.x + threadIdx.x;
    if (i < O3 * CC) split_bf16(W[i], g_w_hi[i], g_w_lo[i]);
}

// ---------------------------------------------------------------------------
// K1: transpose + split x (B,C,P,T) fp32 -> xT bf16 hi/lo [(b,p,t)][c]
// ---------------------------------------------------------------------------
__global__ void __launch_bounds__(256) xsplit_kernel(const float* __restrict__ x) {
    __shared__ uint32_t tile[32][129];
    int p = blockIdx.x, b = blockIdx.y;
    int tid = threadIdx.x;

    const float* src = x + ((size_t)b * CC * PP + p) * TT;
#pragma unroll
    for (int i = 0; i < 4; i++) {
        int idx = tid + i * 256;
        int c = idx >> 3, t4 = idx & 7;
        float4 v = *(const float4*)(src + (size_t)c * PP * TT + t4 * 4);
        float vv[4] = {v.x, v.y, v.z, v.w};
#pragma unroll
        for (int k = 0; k < 4; k++) {
            __nv_bfloat16 hi, lo;
            split_bf16(vv[k], hi, lo);
            tile[t4 * 4 + k][c] =
                (uint32_t)*(const uint16_t*)&hi | ((uint32_t)*(const uint16_t*)&lo << 16);
        }
    }
    __syncthreads();

    size_t nbase = ((size_t)b * PP + p) * TT;
#pragma unroll
    for (int i = 0; i < 2; i++) {
        int idx = tid + i * 256;
        int t = idx >> 4, c8 = idx & 15;
        uint16_t h[8], l[8];
#pragma unroll
        for (int k = 0; k < 8; k++) {
            uint32_t w = tile[t][c8 * 8 + k];
            h[k] = (uint16_t)w;
            l[k] = (uint16_t)(w >> 16);
        }
        size_t off = (nbase + t) * CC + c8 * 8;
        *(uint4*)(g_xt_hi + off) = *(const uint4*)h;
        *(uint4*)(g_xt_lo + off) = *(const uint4*)l;
    }
}

// ---------------------------------------------------------------------------
// MEDIUM GEMM (qkv, dots & out): block 128x128, 128 threads = 4 warps (2m x 2n),
// warp tile 64x64, KT=32, 3-stage ring (96 KB/CTA), 2 CTAs/SM.
// Term rotation: t1(ah,bh) -> t3(al,bh) -> t2(ah,bl), single-buffered frags.
// (Exact R13 structure — proven 240.7us / 70.5% tensor on dots, 754.6us total.)
// transB=0: B [N][K] k-major.  transB=1: B [K][N] n-major (ldsm.trans).
// mode 0: fp32 out (dots). mode 1: scatter to (B,C,P,T) output.
// mode 2: QKV epilogue — dst = bias; kind = blockIdx.y; +bias, q-scale,
//         bf16 split-store into q/k/v attention layouts.
// ---------------------------------------------------------------------------
#define MSTAGE 32768
#define MED_SMEM_REQ (3 * MSTAGE + 1024)

__global__ void __launch_bounds__(128, 2) mma_med_kernel(
    const __nv_bfloat16* __restrict__ Ah, const __nv_bfloat16* __restrict__ Al,
    const __nv_bfloat16* __restrict__ Bh, const __nv_bfloat16* __restrict__ Bl,
    int Kdim, int bLd, int transB, size_t aStride, size_t bStride,
    int mode, float* __restrict__ dst)
{
    extern __shared__ char smem[];
    uint32_t base = (smem_u32(smem) + 1023) & ~1023u;

    int tid = threadIdx.x;
    int wid = tid >> 5, lane = tid & 31;
    int bh = blockIdx.z;
    int m0 = blockIdx.y * 128;
    int n0 = blockIdx.x * 128;

    const __nv_bfloat16* A0h = Ah + (size_t)bh * aStride;
    const __nv_bfloat16* A0l = Al + (size_t)bh * aStride;
    const __nv_bfloat16* B0h = Bh + (size_t)bh * bStride;
    const __nv_bfloat16* B0l = Bl + (size_t)bh * bStride;

    // stage layout: A-hi 8KB | A-lo 8KB | B-hi 8KB | B-lo 8KB
    auto load_tiles = [&](int it) {
        int kk = it * 32;
        uint32_t db = base + (uint32_t)(it % 3) * MSTAGE;
#pragma unroll
        for (int i = 0; i < 8; i++) {            // A: 128 rows x 64B x2 tiles
            const int tile = i >> 2;
            int c = tid + (i & 3) * 128;
            int r = (c >> 2) & 127;
            int j = c & 3;
            const __nv_bfloat16* g = (tile ? A0l : A0h)
                + (size_t)(m0 + r) * Kdim + (kk + j * 8);
            uint32_t s = db + tile * 8192 + r * 64 + (((j ^ ((r >> 1) & 3))) << 4);
            CP_ASYNC16(s, g);
        }
        if (!transB) {
#pragma unroll
            for (int i = 0; i < 8; i++) {        // B: 128 rows x 64B x2
                const int tile = i >> 2;
                int c = tid + (i & 3) * 128;
                int r = (c >> 2) & 127;
                int j = c & 3;
                const __nv_bfloat16* g = (tile ? B0l : B0h)
                    + (size_t)(n0 + r) * bLd + (kk + j * 8);
                uint32_t s = db + 16384 + tile * 8192 + r * 64 + (((j ^ ((r >> 1) & 3))) << 4);
                CP_ASYNC16(s, g);
            }
        } else {
#pragma unroll
            for (int i = 0; i < 8; i++) {        // B: 32 k-rows x 256B x2
                const int tile = i >> 2;
                int c = tid + (i & 3) * 128;
                int r = (c >> 4) & 31;
                int j = c & 15;
                const __nv_bfloat16* g = (tile ? B0l : B0h)
                    + (size_t)(kk + r) * bLd + (n0 + j * 8);
                uint32_t s = db + 16384 + tile * 8192 + r * 256 + (((j ^ (r & 7))) << 4);
                CP_ASYNC16(s, g);
            }
        }
        CP_COMMIT();
    };

    // warp coords: 2m x 2n, warp tile 64x64
    int warp_m = wid & 1, warp_n = wid >> 1;
    int row_in = lane & 7, mat = lane >> 3;
    int a_row = warp_m * 64 + (mat & 1) * 8 + row_in;     // + mt*16
    uint32_t a_salt = (uint32_t)((a_row >> 1) & 3);
    int a_jk = (mat >> 1);
    int b_row = warp_n * 64 + (mat >> 1) * 8 + row_in;    // + ntp*16 (NT)
    uint32_t b_salt = (uint32_t)((b_row >> 1) & 3);
    int b_jk = (mat & 1);
    int t_krow_in = (mat & 1) * 8 + row_in;               // trans-B
    int t_jbase = warp_n * 8 + (mat >> 1);

    float acc[4][8][4];
#pragma unroll
    for (int i = 0; i < 4; i++)
#pragma unroll
        for (int j = 0; j < 8; j++)
#pragma unroll
            for (int k = 0; k < 4; k++) acc[i][j][k] = 0.f;

    // fragment load helpers (single-buffered)
    uint32_t ah[4][4], alf[4][4], bhf[8][2], blf[8][2];
    auto load_a = [&](uint32_t Ab, int kq, uint32_t (*fr)[4]) {
        int aj = kq * 2 + a_jk;
#pragma unroll
        for (int mt = 0; mt < 4; mt++) {
            uint32_t ad = Ab + (uint32_t)(a_row + mt * 16) * 64
                        + (((uint32_t)aj ^ a_salt) << 4);
            LDSM4(fr[mt][0], fr[mt][1], fr[mt][2], fr[mt][3], ad);
        }
    };
    auto load_b = [&](uint32_t Bb, int kq, uint32_t (*fr)[2]) {
        if (!transB) {
            int bj = kq * 2 + b_jk;
#pragma unroll
            for (int ntp = 0; ntp < 4; ntp++) {
                uint32_t ad = Bb + (uint32_t)(b_row + ntp * 16) * 64
                            + (((uint32_t)bj ^ b_salt) << 4);
                uint32_t r0, r1, r2, r3;
                LDSM4(r0, r1, r2, r3, ad);
                fr[2 * ntp][0] = r0; fr[2 * ntp][1] = r1;
                fr[2 * ntp + 1][0] = r2; fr[2 * ntp + 1][1] = r3;
            }
        } else {
            uint32_t krow = (uint32_t)(kq * 16 + t_krow_in);
            uint32_t sw = (uint32_t)(t_krow_in & 7);
#pragma unroll
            for (int ntp = 0; ntp < 4; ntp++) {
                uint32_t j = (uint32_t)(t_jbase + ntp * 2);
                uint32_t ad = Bb + krow * 256 + ((j ^ sw) << 4);
                uint32_t r0, r1, r2, r3;
                LDSM4T(r0, r1, r2, r3, ad);
                fr[2 * ntp][0] = r0; fr[2 * ntp][1] = r1;
                fr[2 * ntp + 1][0] = r2; fr[2 * ntp + 1][1] = r3;
            }
        }
    };
    auto mma_term = [&](uint32_t (*af)[4], uint32_t (*bf)[2]) {
#pragma unroll
        for (int mt = 0; mt < 4; mt++)
#pragma unroll
            for (int nt = 0; nt < 8; nt++)
                MMA16816(acc[mt][nt], af[mt], bf[nt]);
    };

    int iters = Kdim / 32;
    load_tiles(0);
    if (iters > 1) load_tiles(1);

    for (int it = 0; it < iters; it++) {
        if (it + 1 < iters) {
            asm volatile("cp.async.wait_group 1;" ::: "memory");
        } else {
            asm volatile("cp.async.wait_group 0;" ::: "memory");
        }
        __syncthreads();
        if (it + 2 < iters) load_tiles(it + 2);

        uint32_t db = base + (uint32_t)(it % 3) * MSTAGE;
        uint32_t Ah_b = db, Al_b = db + 8192, Bh_b = db + 16384, Bl_b = db + 24576;

        // kq0
        load_a(Ah_b, 0, ah);
        load_b(Bh_b, 0, bhf);
        load_a(Al_b, 0, alf);           // al0 ahead of term1
        mma_term(ah, bhf);              // term1: ah0*bh0
        load_b(Bl_b, 0, blf);           // bl0 ahead of term3
        mma_term(alf, bhf);             // term3: al0*bh0   (bh0 dead after)
        load_b(Bh_b, 1, bhf);           // bh1 — overwrites dead bh0
        mma_term(ah, blf);              // term2: ah0*bl0   (ah0 dead after)
        // kq1
        load_a(Ah_b, 1, ah);            // ah1 — overwrites dead ah0
        load_a(Al_b, 1, alf);           // al1 ahead of term1
        mma_term(ah, bhf);              // term1: ah1*bh1
        load_b(Bl_b, 1, blf);           // bl1 ahead of term3
        mma_term(alf, bhf);             // term3: al1*bh1
        mma_term(ah, blf);              // term2: ah1*bl1
    }

    // ---- epilogue ----
    if (mode == 0) {
        int gm = m0 + warp_m * 64 + (lane >> 2);
#pragma unroll
        for (int mt = 0; mt < 4; mt++)
#pragma unroll
            for (int nt = 0; nt < 8; nt++) {
                int col = n0 + warp_n * 64 + nt * 8 + (lane & 3) * 2;
                int row = gm + mt * 16;
                float* d0 = dst + ((size_t)bh * PP + row) * PP + col;
                *(float2*)d0 = make_float2(acc[mt][nt][0], acc[mt][nt][1]);
                *(float2*)(d0 + 8 * PP) = make_float2(acc[mt][nt][2], acc[mt][nt][3]);
            }
    } else if (mode == 1) {
        int gm = m0 + warp_m * 64 + (lane >> 2);
        int b = bh >> 1, h = bh & 1;
#pragma unroll
        for (int mt = 0; mt < 4; mt++)
#pragma unroll
            for (int nt = 0; nt < 8; nt++) {
                int e = n0 + warp_n * 64 + nt * 8 + (lane & 3) * 2;
                int d = e >> 5, t = e & 31;
                int p = gm + mt * 16;
                float* d0 = dst + (((size_t)b * CC + h * DD + d) * PP + p) * TT + t;
                *(float2*)d0 = make_float2(acc[mt][nt][0], acc[mt][nt][1]);
                *(float2*)(d0 + 8 * TT) = make_float2(acc[mt][nt][2], acc[mt][nt][3]);
            }
    } else {
        // mode 2: QKV epilogue. dst = bias. kind = blockIdx.y (m-tile).
        const float* bias = dst;
        int kind = blockIdx.y;                 // 0=q 1=k 2=v
        __nv_bfloat16* dh = (kind == 0) ? g_q_hi : (kind == 1) ? g_k_hi : g_v_hi;
        __nv_bfloat16* dl = (kind == 0) ? g_q_lo : (kind == 1) ? g_k_lo : g_v_lo;
        float mul = (kind == 0) ? 0.125f : 1.0f;
#pragma unroll
        for (int mt = 0; mt < 4; mt++)
#pragma unroll
            for (int nt = 0; nt < 8; nt++) {
                int n = n0 + warp_n * 64 + nt * 8 + (lane & 3) * 2;
                int b = n >> 14;               // / (P*T)
                int p = (n >> 5) & (PP - 1);
                int t = n & (TT - 1);
#pragma unroll
                for (int half = 0; half < 2; half++) {
                    int o = warp_m * 64 + mt * 16 + (lane >> 2) + half * 8;  // 0..127
                    float bv = __ldg(&bias[kind * CC + o]);
                    int h = o >> 6, d = o & (DD - 1);
                    float v0 = (acc[mt][nt][2 * half + 0] + bv) * mul;
                    float v1 = (acc[mt][nt][2 * half + 1] + bv) * mul;
                    __nv_bfloat16 h2[2], l2[2];
                    split_bf16(v0, h2[0], l2[0]);
                    split_bf16(v1, h2[1], l2[1]);
                    size_t off = (((size_t)b * HH + h) * PP + p) * EE + d * TT + t;
                    *(uint32_t*)(dh + off) = *(const uint32_t*)h2;
                    *(uint32_t*)(dl + off) = *(const uint32_t*)l2;
                }
            }
    }
}

// ---------------------------------------------------------------------------
// K3: row softmax over g_dots — one WARP per row (32 lanes x 16 elements),
// pure shfl reductions, no smem/block barriers. 4 rows per 128-thread block.
// Emits attn as bf16 hi/lo splits.
// ---------------------------------------------------------------------------
__global__ void __launch_bounds__(128) softmax_kernel() {
    int wid = threadIdx.x >> 5, lane = threadIdx.x & 31;
    size_t row = (size_t)blockIdx.x * 4 + wid;
    const float* r = g_dots + row * PP;

    float4 v[4];
#pragma unroll
    for (int i = 0; i < 4; i++) v[i] = ((const float4*)r)[lane + 32 * i];

    float m = -1e30f;
#pragma unroll
    for (int i = 0; i < 4; i++)
        m = fmaxf(m, fmaxf(fmaxf(v[i].x, v[i].y), fmaxf(v[i].z, v[i].w)));
#pragma unroll
    for (int o = 16; o; o >>= 1) m = fmaxf(m, __shfl_xor_sync(0xffffffffu, m, o));

    float s = 0.f;
#pragma unroll
    for (int i = 0; i < 4; i++) {
        v[i].x = expf(v[i].x - m); v[i].y = expf(v[i].y - m);
        v[i].z = expf(v[i].z - m); v[i].w = expf(v[i].w - m);
        s += v[i].x + v[i].y + v[i].z + v[i].w;
    }
#pragma unroll
    for (int o = 16; o; o >>= 1) s += __shfl_xor_sync(0xffffffffu, s, o);
    float inv = 1.0f / s;

#pragma unroll
    for (int i = 0; i < 4; i++) {
        float4 w = v[i];
        w.x *= inv; w.y *= inv; w.z *= inv; w.w *= inv;
        __nv_bfloat16 hi[4], lo[4];
        split_bf16(w.x, hi[0], lo[0]); split_bf16(w.y, hi[1], lo[1]);
        split_bf16(w.z, hi[2], lo[2]); split_bf16(w.w, hi[3], lo[3]);
        size_t e = row * PP + (size_t)(lane + 32 * i) * 4;
        *(uint2*)(g_attn_hi + e) = *(const uint2*)hi;
        *(uint2*)(g_attn_lo + e) = *(const uint2*)lo;
    }
}

// ---------------------------------------------------------------------------
extern "C" void kernel_launch(void* const* d_in, const int* in_sizes, int n_in,
                              void* d_out, int out_size) {
    const float* x = (const float*)d_in[0];
    const float* W = (const float*)d_in[1];
    const float* b = (const float*)d_in[2];
    float* out = (float*)d_out;

    cudaFuncSetAttribute(mma_med_kernel, cudaFuncAttributeMaxDynamicSharedMemorySize, MED_SMEM_REQ);

    wsplit_kernel<<<(O3 * CC + 255) / 256, 256>>>(W);
    xsplit_kernel<<<dim3(PP, BB), 256>>>(x);

    // QKV: D[384, 262144] = W @ xT^T, K=128 — medium kernel, mode 2.
    {
        __nv_bfloat16 *wh, *wl, *xh, *xl;
        cudaGetSymbolAddress((void**)&wh, g_w_hi);
        cudaGetSymbolAddress((void**)&wl, g_w_lo);
        cudaGetSymbolAddress((void**)&xh, g_xt_hi);
        cudaGetSymbolAddress((void**)&xl, g_xt_lo);
        dim3 g((unsigned)(NN / 128), O3 / 128, 1);
        mma_med_kernel<<<g, 128, MED_SMEM_REQ>>>(wh, wl, xh, xl, CC, CC, 0,
                                                 0, 0, 2, (float*)b);
    }

    // dots = Qs @ K^T : M=512, N=512, K=2048, NT, medium kernel mode 0
    {
        float* dots = nullptr;
        cudaGetSymbolAddress((void**)&dots, g_dots);
        __nv_bfloat16 *qh, *ql, *kh, *kl;
        cudaGetSymbolAddress((void**)&qh, g_q_hi);
        cudaGetSymbolAddress((void**)&ql, g_q_lo);
        cudaGetSymbolAddress((void**)&kh, g_k_hi);
        cudaGetSymbolAddress((void**)&kl, g_k_lo);
        dim3 g(PP / 128, PP / 128, BB * HH);
        mma_med_kernel<<<g, 128, MED_SMEM_REQ>>>(qh, ql, kh, kl, EE, EE, 0,
                                                 (size_t)PP * EE, (size_t)PP * EE, 0, dots);
    }

    softmax_kernel<<<BB * HH * PP / 4, 128>>>();

    // out = attn @ V : M=512, N=2048(E), K=512, trans-B, medium kernel mode 1
    {
        __nv_bfloat16 *ah, *al, *vh, *vl;
        cudaGetSymbolAddress((void**)&ah, g_attn_hi);
        cudaGetSymbolAddress((void**)&al, g_attn_lo);
        cudaGetSymbolAddress((void**)&vh, g_v_hi);
        cudaGetSymbolAddress((void**)&vl, g_v_lo);
        dim3 g(EE / 128, PP / 128, BB * HH);
        mma_med_kernel<<<g, 128, MED_SMEM_REQ>>>(ah, al, vh, vl, PP, EE, 1,
                                                 (size_t)PP * PP, (size_t)PP * EE, 1, out);
    }
}